// round 8
// baseline (speedup 1.0000x reference)
#include <cuda_runtime.h>

// Problem constants (fixed shapes for this problem instance)
#define N_NODES 100000
#define NUM_E   1600000
#define IN_C    128
#define HID     32
#define HEADS   4
#define H1DIM   128   // HEADS*HID
#define OUT_C   64
#define NEG_SLOPE 0.2f

#define SCAN_B 512
#define SCAN_NBLK ((N_NODES + SCAN_B - 1) / SCAN_B)   // 196

// ---------------- scratch (device globals; no runtime allocation) -----------
__device__ int   g_is64;                 // edge_index dtype flag (1 = int64)
__device__ int   g_src[NUM_E];
__device__ int   g_dst[NUM_E];
__device__ int   g_psrc[NUM_E];          // CSR-by-dst permuted src ids
__device__ int   g_deg[N_NODES];
__device__ int   g_off[N_NODES + 1];
__device__ int   g_cur[N_NODES];
__device__ int   g_bsum[SCAN_B];
__device__ __align__(16) float g_h1[(size_t)N_NODES * H1DIM];
__device__ __align__(16) float g_out1[(size_t)N_NODES * H1DIM];
__device__ __align__(16) float g_als1[N_NODES * HEADS];
__device__ __align__(16) float g_ald1[N_NODES * HEADS];
__device__ __align__(16) float g_h2[(size_t)N_NODES * OUT_C];
__device__ __align__(16) float g_als2[N_NODES];
__device__ __align__(16) float g_ald2[N_NODES];
__device__ __align__(16) float g_e1[(size_t)NUM_E * HEADS];  // per-edge exp(score) layer1
__device__ __align__(16) float g_e2[NUM_E];                  // per-edge exp(score) layer2

__device__ __forceinline__ float lrelu(float x) {
    return x >= 0.0f ? x : NEG_SLOPE * x;
}

// ---------------- edge_index dtype detection --------------------------------
// If the buffer really is int64 node ids, every sampled 64-bit word is in
// [0, N_NODES). If it is int32, a pair (s, d) read as int64 is s + d*2^32,
// which exceeds N_NODES whenever d > 0 -> flagged int32.
__global__ void k_detect(const void* __restrict__ ei) {
    __shared__ int ok;
    if (threadIdx.x == 0) ok = 1;
    __syncthreads();
    const long long* p = (const long long*)ei;
    for (int i = threadIdx.x; i < 2048; i += blockDim.x) {
        long long v = p[i];
        if (v < 0 || v >= N_NODES) ok = 0;
    }
    __syncthreads();
    if (threadIdx.x == 0) g_is64 = ok;
}

// ---------------- CSR build --------------------------------------------------
__global__ void k_zero_deg() {
    int i = blockIdx.x * blockDim.x + threadIdx.x;
    if (i < N_NODES) g_deg[i] = 0;
}

__global__ void k_convert_hist(const void* __restrict__ ei) {
    int i = blockIdx.x * blockDim.x + threadIdx.x;
    if (i < NUM_E) {
        int s, d;
        if (g_is64) {
            const long long* p = (const long long*)ei;
            s = (int)p[i];
            d = (int)p[NUM_E + i];
        } else {
            const int* p = (const int*)ei;
            s = p[i];
            d = p[NUM_E + i];
        }
        // clamp: turns any residual decode surprise into a rel_err signal
        // instead of a sticky device trap.
        s = min(max(s, 0), N_NODES - 1);
        d = min(max(d, 0), N_NODES - 1);
        g_src[i] = s;
        g_dst[i] = d;
        atomicAdd(&g_deg[d], 1);
    }
}

__global__ void k_scan1() {
    __shared__ int sh[SCAN_B];
    int tid = threadIdx.x;
    int i = blockIdx.x * SCAN_B + tid;
    int v = (i < N_NODES) ? g_deg[i] : 0;
    sh[tid] = v;
    __syncthreads();
    for (int o = 1; o < SCAN_B; o <<= 1) {
        int t = (tid >= o) ? sh[tid - o] : 0;
        __syncthreads();
        sh[tid] += t;
        __syncthreads();
    }
    if (i < N_NODES) g_off[i] = sh[tid] - v;   // block-local exclusive
    if (tid == SCAN_B - 1) g_bsum[blockIdx.x] = sh[tid];
}

__global__ void k_scan2() {
    __shared__ int sh[SCAN_B];
    int tid = threadIdx.x;
    int v = (tid < SCAN_NBLK) ? g_bsum[tid] : 0;
    sh[tid] = v;
    __syncthreads();
    for (int o = 1; o < SCAN_B; o <<= 1) {
        int t = (tid >= o) ? sh[tid - o] : 0;
        __syncthreads();
        sh[tid] += t;
        __syncthreads();
    }
    if (tid < SCAN_NBLK) g_bsum[tid] = sh[tid] - v;   // exclusive block sums
}

__global__ void k_scan3() {
    int i = blockIdx.x * blockDim.x + threadIdx.x;
    if (i < N_NODES) {
        int o = g_off[i] + g_bsum[i / SCAN_B];
        g_off[i] = o;
        g_cur[i] = o;
    }
    if (i == 0) g_off[N_NODES] = NUM_E;
}

__global__ void k_scatter() {
    int i = blockIdx.x * blockDim.x + threadIdx.x;
    if (i < NUM_E) {
        int d = g_dst[i];
        int pos = atomicAdd(&g_cur[d], 1);
        g_psrc[pos] = g_src[i];
    }
}

// ---------------- fp32 GEMM with packed f32x2 FMA ---------------------------
// LAYER 0: C=g_h1 [N,128] = A_param(x) [N,128] * B(W1) [128,128]
// LAYER 1: C=g_h2 [N, 64] = g_out1     [N,128] * B(W2) [128, 64]
// A/C resolved to device globals IN DEVICE CODE.
template <int LAYER, int BM, int BN, int BK, int TM, int TN>
__global__ void k_gemm(const float* __restrict__ A_param, const float* __restrict__ B) {
    constexpr int NT = (BM / TM) * (BN / TN);
    constexpr int M = N_NODES;
    constexpr int K = (LAYER == 0) ? IN_C : H1DIM;
    constexpr int Nc = BN;

    const float* __restrict__ A = (LAYER == 0) ? A_param : (const float*)g_out1;
    float* __restrict__ C = (LAYER == 0) ? (float*)g_h1 : (float*)g_h2;

    __shared__ float As[BK][BM + 4];
    __shared__ float Bs[BK][BN];

    int tid = threadIdx.x;
    int tcol = tid % (BN / TN);
    int trow = tid / (BN / TN);
    int row0 = blockIdx.x * BM;

    unsigned long long acc[TM][TN / 2];
#pragma unroll
    for (int i = 0; i < TM; i++)
#pragma unroll
        for (int j = 0; j < TN / 2; j++) acc[i][j] = 0ull;

    for (int k0 = 0; k0 < K; k0 += BK) {
        // load A tile (BM x BK), transposed into As[k][m]
        for (int idx = tid; idx < BM * (BK / 4); idx += NT) {
            int m = idx / (BK / 4);
            int kq = idx % (BK / 4);
            int gr = row0 + m;
            float4 v = make_float4(0.f, 0.f, 0.f, 0.f);
            if (gr < M) v = *(const float4*)&A[(size_t)gr * K + k0 + kq * 4];
            As[kq * 4 + 0][m] = v.x;
            As[kq * 4 + 1][m] = v.y;
            As[kq * 4 + 2][m] = v.z;
            As[kq * 4 + 3][m] = v.w;
        }
        // load B tile (BK x BN)
        for (int idx = tid; idx < BK * (BN / 4); idx += NT) {
            int kk = idx / (BN / 4);
            int cq = idx % (BN / 4);
            *(float4*)&Bs[kk][cq * 4] = *(const float4*)&B[(size_t)(k0 + kk) * Nc + cq * 4];
        }
        __syncthreads();

#pragma unroll
        for (int k = 0; k < BK; k++) {
            float a[TM];
            *(float4*)&a[0] = *(const float4*)&As[k][trow * TM];
            *(float4*)&a[4] = *(const float4*)&As[k][trow * TM + 4];
            ulonglong2 b01 = *(const ulonglong2*)&Bs[k][tcol * TN];
            ulonglong2 b23 = *(const ulonglong2*)&Bs[k][tcol * TN + 4];
            unsigned long long bp[4] = {b01.x, b01.y, b23.x, b23.y};
#pragma unroll
            for (int i = 0; i < TM; i++) {
                unsigned int ab = __float_as_uint(a[i]);
                unsigned long long a2;
                asm("mov.b64 %0, {%1, %1};" : "=l"(a2) : "r"(ab));
#pragma unroll
                for (int j = 0; j < TN / 2; j++)
                    asm("fma.rn.f32x2 %0, %1, %2, %0;" : "+l"(acc[i][j]) : "l"(a2), "l"(bp[j]));
            }
        }
        __syncthreads();
    }

#pragma unroll
    for (int i = 0; i < TM; i++) {
        int row = row0 + trow * TM + i;
        if (row < M) {
            float o[TN];
#pragma unroll
            for (int j = 0; j < TN / 2; j++) {
                unsigned int lo, hi;
                asm("mov.b64 {%0, %1}, %2;" : "=r"(lo), "=r"(hi) : "l"(acc[i][j]));
                o[2 * j] = __uint_as_float(lo);
                o[2 * j + 1] = __uint_as_float(hi);
            }
            *(float4*)&C[(size_t)row * Nc + tcol * TN] = *(float4*)&o[0];
            *(float4*)&C[(size_t)row * Nc + tcol * TN + 4] = *(float4*)&o[4];
        }
    }
}

// ---------------- attention logits ------------------------------------------
// Layer 1: warp per node; lane covers 4 channels; head = lane>>3.
__global__ void k_logits1(const float* __restrict__ a_src, const float* __restrict__ a_dst) {
    int w = (blockIdx.x * blockDim.x + threadIdx.x) >> 5;
    int lane = threadIdx.x & 31;
    if (w >= N_NODES) return;
    float4 h = ((const float4*)(g_h1 + (size_t)w * H1DIM))[lane];
    float4 asv = ((const float4*)a_src)[lane];
    float4 adv = ((const float4*)a_dst)[lane];
    float ps = h.x * asv.x + h.y * asv.y + h.z * asv.z + h.w * asv.w;
    float pd = h.x * adv.x + h.y * adv.y + h.z * adv.z + h.w * adv.w;
    // reduce within each 8-lane head group
    for (int o = 4; o; o >>= 1) {
        ps += __shfl_down_sync(0xffffffffu, ps, o);
        pd += __shfl_down_sync(0xffffffffu, pd, o);
    }
    if ((lane & 7) == 0) {
        int head = lane >> 3;
        g_als1[w * HEADS + head] = ps;
        g_ald1[w * HEADS + head] = pd;
    }
}

// Layer 2: warp per node; lanes 0..15 cover 64 channels.
__global__ void k_logits2(const float* __restrict__ a_src, const float* __restrict__ a_dst) {
    int w = (blockIdx.x * blockDim.x + threadIdx.x) >> 5;
    int lane = threadIdx.x & 31;
    if (w >= N_NODES) return;
    float ps = 0.f, pd = 0.f;
    if (lane < 16) {
        float4 h = ((const float4*)(g_h2 + (size_t)w * OUT_C))[lane];
        float4 asv = ((const float4*)a_src)[lane];
        float4 adv = ((const float4*)a_dst)[lane];
        ps = h.x * asv.x + h.y * asv.y + h.z * asv.z + h.w * asv.w;
        pd = h.x * adv.x + h.y * adv.y + h.z * adv.z + h.w * adv.w;
    }
    for (int o = 8; o; o >>= 1) {
        ps += __shfl_xor_sync(0xffffffffu, ps, o);
        pd += __shfl_xor_sync(0xffffffffu, pd, o);
    }
    if (lane == 0) {
        g_als2[w] = ps;
        g_ald2[w] = pd;
    }
}

// ---------------- aggregation (warp per destination node) -------------------
// Layer 1: 4 heads x 32 ch. Each lane owns 4 channels (float4); head = lane>>3.
__global__ void k_agg1(const float* __restrict__ bias) {
    int w = (blockIdx.x * blockDim.x + threadIdx.x) >> 5;
    int lane = threadIdx.x & 31;
    if (w >= N_NODES) return;
    int beg = g_off[w], end = g_off[w + 1];
    float4 ad = ((const float4*)g_ald1)[w];

    // pass 1: exp(leaky(score)) per edge (lane-strided), store, accumulate sums
    float4 s = make_float4(0.f, 0.f, 0.f, 0.f);
    for (int j = beg + lane; j < end; j += 32) {
        int src = g_psrc[j];
        float4 asv = ((const float4*)g_als1)[src];
        float4 e;
        e.x = __expf(lrelu(asv.x + ad.x));
        e.y = __expf(lrelu(asv.y + ad.y));
        e.z = __expf(lrelu(asv.z + ad.z));
        e.w = __expf(lrelu(asv.w + ad.w));
        ((float4*)g_e1)[j] = e;
        s.x += e.x; s.y += e.y; s.z += e.z; s.w += e.w;
    }
    for (int o = 16; o; o >>= 1) {
        s.x += __shfl_xor_sync(0xffffffffu, s.x, o);
        s.y += __shfl_xor_sync(0xffffffffu, s.y, o);
        s.z += __shfl_xor_sync(0xffffffffu, s.z, o);
        s.w += __shfl_xor_sync(0xffffffffu, s.w, o);
    }
    __threadfence_block();
    __syncwarp();

    int head = lane >> 3;
    float sh = (head == 0) ? s.x : (head == 1) ? s.y : (head == 2) ? s.z : s.w;
    float inv = 1.0f / (sh + 1e-16f);

    // pass 2: weighted gather-accumulate
    float4 acc = make_float4(0.f, 0.f, 0.f, 0.f);
    const float4* hp = (const float4*)g_h1;
    for (int j = beg; j < end; ++j) {
        float4 e4 = ((const float4*)g_e1)[j];
        float ev = (head == 0) ? e4.x : (head == 1) ? e4.y : (head == 2) ? e4.z : e4.w;
        float wt = ev * inv;
        int src = g_psrc[j];
        float4 hv = hp[(size_t)src * (H1DIM / 4) + lane];
        acc.x += hv.x * wt; acc.y += hv.y * wt; acc.z += hv.z * wt; acc.w += hv.w * wt;
    }

    float4 bv = ((const float4*)bias)[lane];
    float4 v;
    v.x = acc.x + bv.x; v.y = acc.y + bv.y; v.z = acc.z + bv.z; v.w = acc.w + bv.w;
    // ELU
    v.x = v.x > 0.f ? v.x : expm1f(v.x);
    v.y = v.y > 0.f ? v.y : expm1f(v.y);
    v.z = v.z > 0.f ? v.z : expm1f(v.z);
    v.w = v.w > 0.f ? v.w : expm1f(v.w);
    ((float4*)g_out1)[(size_t)w * (H1DIM / 4) + lane] = v;
}

// Layer 2: 1 head x 64 ch. Each lane owns 2 channels (float2).
__global__ void k_agg2(const float* __restrict__ bias, float* __restrict__ out) {
    int w = (blockIdx.x * blockDim.x + threadIdx.x) >> 5;
    int lane = threadIdx.x & 31;
    if (w >= N_NODES) return;
    int beg = g_off[w], end = g_off[w + 1];
    float ad = g_ald2[w];

    float s = 0.f;
    for (int j = beg + lane; j < end; j += 32) {
        int src = g_psrc[j];
        float e = __expf(lrelu(g_als2[src] + ad));
        g_e2[j] = e;
        s += e;
    }
    for (int o = 16; o; o >>= 1) s += __shfl_xor_sync(0xffffffffu, s, o);
    __threadfence_block();
    __syncwarp();
    float inv = 1.0f / (s + 1e-16f);

    float2 acc = make_float2(0.f, 0.f);
    const float2* hp = (const float2*)g_h2;
    for (int j = beg; j < end; ++j) {
        float wt = g_e2[j] * inv;
        int src = g_psrc[j];
        float2 hv = hp[(size_t)src * (OUT_C / 2) + lane];
        acc.x += hv.x * wt;
        acc.y += hv.y * wt;
    }
    float2 bv = ((const float2*)bias)[lane];
    float2 v = make_float2(acc.x + bv.x, acc.y + bv.y);
    ((float2*)out)[(size_t)w * (OUT_C / 2) + lane] = v;
}

// ---------------- launch -----------------------------------------------------
extern "C" void kernel_launch(void* const* d_in, const int* in_sizes, int n_in,
                              void* d_out, int out_size) {
    const float*      x      = (const float*)d_in[0];
    const void*       eidx   = d_in[1];               // int32 or int64, detected on device
    const float*      W1     = (const float*)d_in[2];
    const float*      a_src1 = (const float*)d_in[3];
    const float*      a_dst1 = (const float*)d_in[4];
    const float*      b1     = (const float*)d_in[5];
    const float*      W2     = (const float*)d_in[6];
    const float*      a_src2 = (const float*)d_in[7];
    const float*      a_dst2 = (const float*)d_in[8];
    const float*      b2     = (const float*)d_in[9];
    float*            out    = (float*)d_out;

    const int node_blocks = (N_NODES + 255) / 256;
    const int edge_blocks = (NUM_E + 255) / 256;
    const int warp_blocks = (N_NODES * 32 + 255) / 256;   // warp-per-node kernels
    const int gemm_blocks = (N_NODES + 127) / 128;

    // CSR build (per-launch; graph replays must redo it)
    k_detect<<<1, 256>>>(eidx);
    k_zero_deg<<<node_blocks, 256>>>();
    k_convert_hist<<<edge_blocks, 256>>>(eidx);
    k_scan1<<<SCAN_NBLK, SCAN_B>>>();
    k_scan2<<<1, SCAN_B>>>();
    k_scan3<<<node_blocks, 256>>>();
    k_scatter<<<edge_blocks, 256>>>();

    // Layer 1
    k_gemm<0, 128, 128, 16, 8, 8><<<gemm_blocks, 256>>>(x, W1);
    k_logits1<<<warp_blocks, 256>>>(a_src1, a_dst1);
    k_agg1<<<warp_blocks, 256>>>(b1);

    // Layer 2
    k_gemm<1, 128, 64, 16, 8, 8><<<gemm_blocks, 128>>>(nullptr, W2);
    k_logits2<<<warp_blocks, 256>>>(a_src2, a_dst2);
    k_agg2<<<warp_blocks, 256>>>(b2, out);
}

// round 9
// speedup vs baseline: 1.3802x; 1.3802x over previous
#include <cuda_runtime.h>

// Problem constants (fixed shapes for this problem instance)
#define N_NODES 100000
#define NUM_E   1600000
#define IN_C    128
#define HID     32
#define HEADS   4
#define H1DIM   128   // HEADS*HID
#define OUT_C   64
#define NEG_SLOPE 0.2f

#define SCAN_B 512
#define SCAN_NBLK ((N_NODES + SCAN_B - 1) / SCAN_B)   // 196

// ---------------- scratch (device globals; no runtime allocation) -----------
__device__ int   g_is64;                 // edge_index dtype flag (1 = int64)
__device__ int   g_src[NUM_E];
__device__ int   g_dst[NUM_E];
__device__ int   g_psrc[NUM_E];          // CSR-by-dst permuted src ids
__device__ int   g_deg[N_NODES];
__device__ int   g_off[N_NODES + 1];
__device__ int   g_cur[N_NODES];
__device__ int   g_bsum[SCAN_B];
__device__ __align__(16) float g_h1[(size_t)N_NODES * H1DIM];
__device__ __align__(16) float g_out1[(size_t)N_NODES * H1DIM];
__device__ __align__(16) float g_als1[N_NODES * HEADS];
__device__ __align__(16) float g_ald1[N_NODES * HEADS];
__device__ __align__(16) float g_h2[(size_t)N_NODES * OUT_C];
__device__ __align__(16) float g_als2[N_NODES];
__device__ __align__(16) float g_ald2[N_NODES];

__device__ __forceinline__ float lrelu(float x) {
    return x >= 0.0f ? x : NEG_SLOPE * x;
}

__device__ __forceinline__ unsigned int f2tf32(float x) {
    unsigned int r;
    asm("cvt.rna.tf32.f32 %0, %1;" : "=r"(r) : "f"(x));
    return r;
}

// ---------------- edge_index dtype detection --------------------------------
__global__ void k_detect(const void* __restrict__ ei) {
    __shared__ int ok;
    if (threadIdx.x == 0) ok = 1;
    __syncthreads();
    const long long* p = (const long long*)ei;
    for (int i = threadIdx.x; i < 2048; i += blockDim.x) {
        long long v = p[i];
        if (v < 0 || v >= N_NODES) ok = 0;
    }
    __syncthreads();
    if (threadIdx.x == 0) g_is64 = ok;
}

// ---------------- CSR build --------------------------------------------------
__global__ void k_zero_deg() {
    int i = blockIdx.x * blockDim.x + threadIdx.x;
    if (i < N_NODES) g_deg[i] = 0;
}

__global__ void k_convert_hist(const void* __restrict__ ei) {
    int i = blockIdx.x * blockDim.x + threadIdx.x;
    if (i < NUM_E) {
        int s, d;
        if (g_is64) {
            const long long* p = (const long long*)ei;
            s = (int)p[i];
            d = (int)p[NUM_E + i];
        } else {
            const int* p = (const int*)ei;
            s = p[i];
            d = p[NUM_E + i];
        }
        s = min(max(s, 0), N_NODES - 1);
        d = min(max(d, 0), N_NODES - 1);
        g_src[i] = s;
        g_dst[i] = d;
        atomicAdd(&g_deg[d], 1);
    }
}

__global__ void k_scan1() {
    __shared__ int sh[SCAN_B];
    int tid = threadIdx.x;
    int i = blockIdx.x * SCAN_B + tid;
    int v = (i < N_NODES) ? g_deg[i] : 0;
    sh[tid] = v;
    __syncthreads();
    for (int o = 1; o < SCAN_B; o <<= 1) {
        int t = (tid >= o) ? sh[tid - o] : 0;
        __syncthreads();
        sh[tid] += t;
        __syncthreads();
    }
    if (i < N_NODES) g_off[i] = sh[tid] - v;
    if (tid == SCAN_B - 1) g_bsum[blockIdx.x] = sh[tid];
}

__global__ void k_scan2() {
    __shared__ int sh[SCAN_B];
    int tid = threadIdx.x;
    int v = (tid < SCAN_NBLK) ? g_bsum[tid] : 0;
    sh[tid] = v;
    __syncthreads();
    for (int o = 1; o < SCAN_B; o <<= 1) {
        int t = (tid >= o) ? sh[tid - o] : 0;
        __syncthreads();
        sh[tid] += t;
        __syncthreads();
    }
    if (tid < SCAN_NBLK) g_bsum[tid] = sh[tid] - v;
}

__global__ void k_scan3() {
    int i = blockIdx.x * blockDim.x + threadIdx.x;
    if (i < N_NODES) {
        int o = g_off[i] + g_bsum[i / SCAN_B];
        g_off[i] = o;
        g_cur[i] = o;
    }
    if (i == 0) g_off[N_NODES] = NUM_E;
}

__global__ void k_scatter() {
    int i = blockIdx.x * blockDim.x + threadIdx.x;
    if (i < NUM_E) {
        int d = g_dst[i];
        int pos = atomicAdd(&g_cur[d], 1);
        g_psrc[pos] = g_src[i];
    }
}

// ---------------- tf32 tensor-core GEMM --------------------------------------
// LAYER 0: C=g_h1 [N,128] = A_param(x) [N,128] * B(W1) [128,128]
// LAYER 1: C=g_h2 [N, 64] = g_out1     [N,128] * B(W2) [128, 64]
// mma.sync.aligned.m16n8k8 tf32. Block = 256 threads (8 warps), tile BM=128.
// Warp grid 4(m) x 2(n): warp covers 32 rows x BN/2 cols.
template <int LAYER, int BN>
__global__ void __launch_bounds__(256) k_gemm_tc(const float* __restrict__ A_param,
                                                 const float* __restrict__ B) {
    constexpr int BM = 128;
    constexpr int BK = 32;
    constexpr int K = 128;
    constexpr int M = N_NODES;
    constexpr int NT = BN / 2 / 8;   // n-tiles per warp (8 or 4)
    constexpr int APAD = 4;

    const float* __restrict__ A = (LAYER == 0) ? A_param : (const float*)g_out1;
    float* __restrict__ C = (LAYER == 0) ? (float*)g_h1 : (float*)g_h2;

    __shared__ unsigned int Ast[BK][BM + APAD];   // transposed: Ast[k][m]
    __shared__ unsigned int Bs[BK][BN + APAD];    // Bs[k][n]

    int tid = threadIdx.x;
    int wid = tid >> 5;
    int lane = tid & 31;
    int gid = lane >> 2;     // 0..7
    int tig = lane & 3;      // 0..3
    int warp_m = wid >> 1;   // 0..3
    int warp_n = wid & 1;    // 0..1
    int m0 = warp_m * 32;
    int n0 = warp_n * (BN / 2);
    int row0 = blockIdx.x * BM;

    float acc[2][NT][4];
#pragma unroll
    for (int mt = 0; mt < 2; mt++)
#pragma unroll
        for (int nt = 0; nt < NT; nt++)
#pragma unroll
            for (int c = 0; c < 4; c++) acc[mt][nt][c] = 0.f;

    for (int k0 = 0; k0 < K; k0 += BK) {
        // fill A tile (BM x BK) transposed, with tf32 convert
#pragma unroll
        for (int idx = tid; idx < BM * (BK / 4); idx += 256) {
            int m = idx >> 3;            // BK/4 == 8
            int kq = idx & 7;
            int gr = row0 + m;
            float4 v = make_float4(0.f, 0.f, 0.f, 0.f);
            if (gr < M) v = *(const float4*)&A[(size_t)gr * K + k0 + kq * 4];
            Ast[kq * 4 + 0][m] = f2tf32(v.x);
            Ast[kq * 4 + 1][m] = f2tf32(v.y);
            Ast[kq * 4 + 2][m] = f2tf32(v.z);
            Ast[kq * 4 + 3][m] = f2tf32(v.w);
        }
        // fill B tile (BK x BN)
#pragma unroll
        for (int idx = tid; idx < BK * (BN / 4); idx += 256) {
            int kk = idx / (BN / 4);
            int cq = idx % (BN / 4);
            float4 v = *(const float4*)&B[(size_t)(k0 + kk) * BN + cq * 4];
            Bs[kk][cq * 4 + 0] = f2tf32(v.x);
            Bs[kk][cq * 4 + 1] = f2tf32(v.y);
            Bs[kk][cq * 4 + 2] = f2tf32(v.z);
            Bs[kk][cq * 4 + 3] = f2tf32(v.w);
        }
        __syncthreads();

#pragma unroll
        for (int ks = 0; ks < BK / 8; ks++) {
            unsigned int a[2][4];
#pragma unroll
            for (int mt = 0; mt < 2; mt++) {
                int mb = m0 + mt * 16 + gid;
                a[mt][0] = Ast[ks * 8 + tig][mb];
                a[mt][1] = Ast[ks * 8 + tig][mb + 8];
                a[mt][2] = Ast[ks * 8 + tig + 4][mb];
                a[mt][3] = Ast[ks * 8 + tig + 4][mb + 8];
            }
#pragma unroll
            for (int nt = 0; nt < NT; nt++) {
                unsigned int b0 = Bs[ks * 8 + tig][n0 + nt * 8 + gid];
                unsigned int b1 = Bs[ks * 8 + tig + 4][n0 + nt * 8 + gid];
#pragma unroll
                for (int mt = 0; mt < 2; mt++) {
                    asm("mma.sync.aligned.m16n8k8.row.col.f32.tf32.tf32.f32 "
                        "{%0,%1,%2,%3}, {%4,%5,%6,%7}, {%8,%9}, {%0,%1,%2,%3};"
                        : "+f"(acc[mt][nt][0]), "+f"(acc[mt][nt][1]),
                          "+f"(acc[mt][nt][2]), "+f"(acc[mt][nt][3])
                        : "r"(a[mt][0]), "r"(a[mt][1]), "r"(a[mt][2]), "r"(a[mt][3]),
                          "r"(b0), "r"(b1));
                }
            }
        }
        __syncthreads();
    }

    // epilogue: c0/c1 at (row, 2tig), (row, 2tig+1); c2/c3 at row+8
#pragma unroll
    for (int mt = 0; mt < 2; mt++) {
#pragma unroll
        for (int nt = 0; nt < NT; nt++) {
            int col = n0 + nt * 8 + 2 * tig;
            int r0 = row0 + m0 + mt * 16 + gid;
            if (r0 < M)
                *(float2*)&C[(size_t)r0 * BN + col] = make_float2(acc[mt][nt][0], acc[mt][nt][1]);
            if (r0 + 8 < M)
                *(float2*)&C[(size_t)(r0 + 8) * BN + col] = make_float2(acc[mt][nt][2], acc[mt][nt][3]);
        }
    }
}

// ---------------- attention logits ------------------------------------------
__global__ void k_logits1(const float* __restrict__ a_src, const float* __restrict__ a_dst) {
    int w = (blockIdx.x * blockDim.x + threadIdx.x) >> 5;
    int lane = threadIdx.x & 31;
    if (w >= N_NODES) return;
    float4 h = ((const float4*)(g_h1 + (size_t)w * H1DIM))[lane];
    float4 asv = ((const float4*)a_src)[lane];
    float4 adv = ((const float4*)a_dst)[lane];
    float ps = h.x * asv.x + h.y * asv.y + h.z * asv.z + h.w * asv.w;
    float pd = h.x * adv.x + h.y * adv.y + h.z * adv.z + h.w * adv.w;
    for (int o = 4; o; o >>= 1) {
        ps += __shfl_down_sync(0xffffffffu, ps, o);
        pd += __shfl_down_sync(0xffffffffu, pd, o);
    }
    if ((lane & 7) == 0) {
        int head = lane >> 3;
        g_als1[w * HEADS + head] = ps;
        g_ald1[w * HEADS + head] = pd;
    }
}

__global__ void k_logits2(const float* __restrict__ a_src, const float* __restrict__ a_dst) {
    int w = (blockIdx.x * blockDim.x + threadIdx.x) >> 5;
    int lane = threadIdx.x & 31;
    if (w >= N_NODES) return;
    float ps = 0.f, pd = 0.f;
    if (lane < 16) {
        float4 h = ((const float4*)(g_h2 + (size_t)w * OUT_C))[lane];
        float4 asv = ((const float4*)a_src)[lane];
        float4 adv = ((const float4*)a_dst)[lane];
        ps = h.x * asv.x + h.y * asv.y + h.z * asv.z + h.w * asv.w;
        pd = h.x * adv.x + h.y * adv.y + h.z * adv.z + h.w * adv.w;
    }
    for (int o = 8; o; o >>= 1) {
        ps += __shfl_xor_sync(0xffffffffu, ps, o);
        pd += __shfl_xor_sync(0xffffffffu, pd, o);
    }
    if (lane == 0) {
        g_als2[w] = ps;
        g_ald2[w] = pd;
    }
}

// ---------------- aggregation (warp per destination node) -------------------
// No per-edge weight scratch: exp recomputed in pass 2 (MUFU is cheap per
// warp-instruction; saves the g_e1/g_e2 store+reload traffic).
__global__ void k_agg1(const float* __restrict__ bias) {
    int w = (blockIdx.x * blockDim.x + threadIdx.x) >> 5;
    int lane = threadIdx.x & 31;
    if (w >= N_NODES) return;
    int beg = g_off[w], end = g_off[w + 1];
    float4 ad = ((const float4*)g_ald1)[w];

    // pass 1: per-head exp sums (lane-strided over edges)
    float4 s = make_float4(0.f, 0.f, 0.f, 0.f);
    for (int j = beg + lane; j < end; j += 32) {
        int src = g_psrc[j];
        float4 asv = ((const float4*)g_als1)[src];
        s.x += __expf(lrelu(asv.x + ad.x));
        s.y += __expf(lrelu(asv.y + ad.y));
        s.z += __expf(lrelu(asv.z + ad.z));
        s.w += __expf(lrelu(asv.w + ad.w));
    }
    for (int o = 16; o; o >>= 1) {
        s.x += __shfl_xor_sync(0xffffffffu, s.x, o);
        s.y += __shfl_xor_sync(0xffffffffu, s.y, o);
        s.z += __shfl_xor_sync(0xffffffffu, s.z, o);
        s.w += __shfl_xor_sync(0xffffffffu, s.w, o);
    }

    int head = lane >> 3;
    float sh = (head == 0) ? s.x : (head == 1) ? s.y : (head == 2) ? s.z : s.w;
    float adh = (head == 0) ? ad.x : (head == 1) ? ad.y : (head == 2) ? ad.z : ad.w;
    float inv = 1.0f / (sh + 1e-16f);

    // pass 2: weighted gather-accumulate, exp recomputed per lane
    float4 acc = make_float4(0.f, 0.f, 0.f, 0.f);
    const float4* hp = (const float4*)g_h1;
    for (int j = beg; j < end; ++j) {
        int src = g_psrc[j];
        float als = g_als1[src * HEADS + head];
        float wt = __expf(lrelu(als + adh)) * inv;
        float4 hv = hp[(size_t)src * (H1DIM / 4) + lane];
        acc.x += hv.x * wt; acc.y += hv.y * wt; acc.z += hv.z * wt; acc.w += hv.w * wt;
    }

    float4 bv = ((const float4*)bias)[lane];
    float4 v;
    v.x = acc.x + bv.x; v.y = acc.y + bv.y; v.z = acc.z + bv.z; v.w = acc.w + bv.w;
    v.x = v.x > 0.f ? v.x : expm1f(v.x);
    v.y = v.y > 0.f ? v.y : expm1f(v.y);
    v.z = v.z > 0.f ? v.z : expm1f(v.z);
    v.w = v.w > 0.f ? v.w : expm1f(v.w);
    ((float4*)g_out1)[(size_t)w * (H1DIM / 4) + lane] = v;
}

__global__ void k_agg2(const float* __restrict__ bias, float* __restrict__ out) {
    int w = (blockIdx.x * blockDim.x + threadIdx.x) >> 5;
    int lane = threadIdx.x & 31;
    if (w >= N_NODES) return;
    int beg = g_off[w], end = g_off[w + 1];
    float ad = g_ald2[w];

    float s = 0.f;
    for (int j = beg + lane; j < end; j += 32) {
        int src = g_psrc[j];
        s += __expf(lrelu(g_als2[src] + ad));
    }
    for (int o = 16; o; o >>= 1) s += __shfl_xor_sync(0xffffffffu, s, o);
    float inv = 1.0f / (s + 1e-16f);

    float2 acc = make_float2(0.f, 0.f);
    const float2* hp = (const float2*)g_h2;
    for (int j = beg; j < end; ++j) {
        int src = g_psrc[j];
        float wt = __expf(lrelu(g_als2[src] + ad)) * inv;
        float2 hv = hp[(size_t)src * (OUT_C / 2) + lane];
        acc.x += hv.x * wt;
        acc.y += hv.y * wt;
    }
    float2 bv = ((const float2*)bias)[lane];
    ((float2*)out)[(size_t)w * (OUT_C / 2) + lane] = make_float2(acc.x + bv.x, acc.y + bv.y);
}

// ---------------- launch -----------------------------------------------------
extern "C" void kernel_launch(void* const* d_in, const int* in_sizes, int n_in,
                              void* d_out, int out_size) {
    const float*      x      = (const float*)d_in[0];
    const void*       eidx   = d_in[1];               // int32 or int64, detected on device
    const float*      W1     = (const float*)d_in[2];
    const float*      a_src1 = (const float*)d_in[3];
    const float*      a_dst1 = (const float*)d_in[4];
    const float*      b1     = (const float*)d_in[5];
    const float*      W2     = (const float*)d_in[6];
    const float*      a_src2 = (const float*)d_in[7];
    const float*      a_dst2 = (const float*)d_in[8];
    const float*      b2     = (const float*)d_in[9];
    float*            out    = (float*)d_out;

    const int node_blocks = (N_NODES + 255) / 256;
    const int edge_blocks = (NUM_E + 255) / 256;
    const int warp_blocks = (N_NODES * 32 + 255) / 256;
    const int gemm_blocks = (N_NODES + 127) / 128;

    // CSR build
    k_detect<<<1, 256>>>(eidx);
    k_zero_deg<<<node_blocks, 256>>>();
    k_convert_hist<<<edge_blocks, 256>>>(eidx);
    k_scan1<<<SCAN_NBLK, SCAN_B>>>();
    k_scan2<<<1, SCAN_B>>>();
    k_scan3<<<node_blocks, 256>>>();
    k_scatter<<<edge_blocks, 256>>>();

    // Layer 1
    k_gemm_tc<0, 128><<<gemm_blocks, 256>>>(x, W1);
    k_logits1<<<warp_blocks, 256>>>(a_src1, a_dst1);
    k_agg1<<<warp_blocks, 256>>>(b1);

    // Layer 2
    k_gemm_tc<1, 64><<<gemm_blocks, 256>>>(nullptr, W2);
    k_logits2<<<warp_blocks, 256>>>(a_src2, a_dst2);
    k_agg2<<<warp_blocks, 256>>>(b2, out);
}

// round 13
// speedup vs baseline: 1.7293x; 1.2529x over previous
#include <cuda_runtime.h>

// Problem constants (fixed shapes for this problem instance)
#define N_NODES 100000
#define NUM_E   1600000
#define IN_C    128
#define HID     32
#define HEADS   4
#define H1DIM   128   // HEADS*HID
#define OUT_C   64
#define NEG_SLOPE 0.2f

#define SCAN_B 512
#define SCAN_NBLK ((N_NODES + SCAN_B - 1) / SCAN_B)   // 196
#define NODE_BLOCKS ((N_NODES + 255) / 256)

// ---------------- scratch (device globals; no runtime allocation) -----------
__device__ int   g_is64;                 // edge_index dtype flag (1 = int64)
__device__ int   g_src[NUM_E];
__device__ int   g_dst[NUM_E];
__device__ int   g_psrc[NUM_E];          // CSR-by-dst permuted src ids
__device__ int   g_deg[N_NODES];
__device__ int   g_off[N_NODES + 1];
__device__ int   g_cur[N_NODES];
__device__ int   g_bsum[SCAN_B];
__device__ __align__(16) float g_h1[(size_t)N_NODES * H1DIM];
__device__ __align__(16) float g_out1[(size_t)N_NODES * H1DIM];
__device__ __align__(16) float g_als1[N_NODES * HEADS];
__device__ __align__(16) float g_ald1[N_NODES * HEADS];
__device__ __align__(16) float g_h2[(size_t)N_NODES * OUT_C];
__device__ __align__(16) float g_als2[N_NODES];
__device__ __align__(16) float g_ald2[N_NODES];

__device__ __forceinline__ float lrelu(float x) {
    return x >= 0.0f ? x : NEG_SLOPE * x;
}

__device__ __forceinline__ unsigned int f2tf32(float x) {
    unsigned int r;
    asm("cvt.rna.tf32.f32 %0, %1;" : "=r"(r) : "f"(x));
    return r;
}

// ---------------- CSR build --------------------------------------------------
// zero_deg fused with dtype detection (last block does detect).
__global__ void k_zero_detect(const void* __restrict__ ei) {
    if (blockIdx.x == NODE_BLOCKS) {
        __shared__ int ok;
        if (threadIdx.x == 0) ok = 1;
        __syncthreads();
        const long long* p = (const long long*)ei;
        for (int i = threadIdx.x; i < 2048; i += blockDim.x) {
            long long v = p[i];
            if (v < 0 || v >= N_NODES) ok = 0;
        }
        __syncthreads();
        if (threadIdx.x == 0) g_is64 = ok;
        return;
    }
    int i = blockIdx.x * blockDim.x + threadIdx.x;
    if (i < N_NODES) g_deg[i] = 0;
}

__global__ void k_convert_hist(const void* __restrict__ ei) {
    int i = blockIdx.x * blockDim.x + threadIdx.x;
    if (i < NUM_E) {
        int s, d;
        if (g_is64) {
            const long long* p = (const long long*)ei;
            s = (int)p[i];
            d = (int)p[NUM_E + i];
        } else {
            const int* p = (const int*)ei;
            s = p[i];
            d = p[NUM_E + i];
        }
        s = min(max(s, 0), N_NODES - 1);
        d = min(max(d, 0), N_NODES - 1);
        g_src[i] = s;
        g_dst[i] = d;
        atomicAdd(&g_deg[d], 1);
    }
}

__global__ void k_scan1() {
    __shared__ int sh[SCAN_B];
    int tid = threadIdx.x;
    int i = blockIdx.x * SCAN_B + tid;
    int v = (i < N_NODES) ? g_deg[i] : 0;
    sh[tid] = v;
    __syncthreads();
    for (int o = 1; o < SCAN_B; o <<= 1) {
        int t = (tid >= o) ? sh[tid - o] : 0;
        __syncthreads();
        sh[tid] += t;
        __syncthreads();
    }
    if (i < N_NODES) g_off[i] = sh[tid] - v;
    if (tid == SCAN_B - 1) g_bsum[blockIdx.x] = sh[tid];
}

__global__ void k_scan2() {
    __shared__ int sh[SCAN_B];
    int tid = threadIdx.x;
    int v = (tid < SCAN_NBLK) ? g_bsum[tid] : 0;
    sh[tid] = v;
    __syncthreads();
    for (int o = 1; o < SCAN_B; o <<= 1) {
        int t = (tid >= o) ? sh[tid - o] : 0;
        __syncthreads();
        sh[tid] += t;
        __syncthreads();
    }
    if (tid < SCAN_NBLK) g_bsum[tid] = sh[tid] - v;
}

__global__ void k_scan3() {
    int i = blockIdx.x * blockDim.x + threadIdx.x;
    if (i < N_NODES) {
        int o = g_off[i] + g_bsum[i / SCAN_B];
        g_off[i] = o;
        g_cur[i] = o;
    }
    if (i == 0) g_off[N_NODES] = NUM_E;
}

__global__ void k_scatter() {
    int i = blockIdx.x * blockDim.x + threadIdx.x;
    if (i < NUM_E) {
        int d = g_dst[i];
        int pos = atomicAdd(&g_cur[d], 1);
        g_psrc[pos] = g_src[i];
    }
}

// ---------------- tf32 tensor-core GEMM with fused attention logits ----------
// LAYER 0: C=g_h1 [N,128] = A_param(x) [N,128] * W1; logits -> g_als1/g_ald1
// LAYER 1: C=g_h2 [N, 64] = g_out1     [N,128] * W2; logits -> g_als2/g_ald2
// mma.sync.aligned.m16n8k8 tf32. 256 threads, BM=128, warps 4(m) x 2(n).
template <int LAYER, int BN>
__global__ void __launch_bounds__(256) k_gemm_tc(const float* __restrict__ A_param,
                                                 const float* __restrict__ B,
                                                 const float* __restrict__ a_s,
                                                 const float* __restrict__ a_d) {
    constexpr int BM = 128;
    constexpr int BK = 32;
    constexpr int K = 128;
    constexpr int M = N_NODES;
    constexpr int NT = BN / 2 / 8;   // n-tiles per warp (8 or 4)
    constexpr int APAD = 4;

    const float* __restrict__ A = (LAYER == 0) ? A_param : (const float*)g_out1;
    float* __restrict__ C = (LAYER == 0) ? (float*)g_h1 : (float*)g_h2;

    __shared__ unsigned int Ast[BK][BM + APAD];   // transposed: Ast[k][m]
    __shared__ unsigned int Bs[BK][BN + APAD];    // Bs[k][n]
    __shared__ float sP[BM], sD[BM];              // layer-2 logit combine

    int tid = threadIdx.x;
    int wid = tid >> 5;
    int lane = tid & 31;
    int gid = lane >> 2;     // 0..7
    int tig = lane & 3;      // 0..3
    int warp_m = wid >> 1;   // 0..3
    int warp_n = wid & 1;    // 0..1
    int m0 = warp_m * 32;
    int n0 = warp_n * (BN / 2);
    int row0 = blockIdx.x * BM;

    if (LAYER == 1 && tid < BM) { sP[tid] = 0.f; sD[tid] = 0.f; }

    float acc[2][NT][4];
#pragma unroll
    for (int mt = 0; mt < 2; mt++)
#pragma unroll
        for (int nt = 0; nt < NT; nt++)
#pragma unroll
            for (int c = 0; c < 4; c++) acc[mt][nt][c] = 0.f;

    for (int k0 = 0; k0 < K; k0 += BK) {
        // fill A tile (BM x BK) transposed, with tf32 convert
#pragma unroll
        for (int idx = tid; idx < BM * (BK / 4); idx += 256) {
            int m = idx >> 3;            // BK/4 == 8
            int kq = idx & 7;
            int gr = row0 + m;
            float4 v = make_float4(0.f, 0.f, 0.f, 0.f);
            if (gr < M) v = *(const float4*)&A[(size_t)gr * K + k0 + kq * 4];
            Ast[kq * 4 + 0][m] = f2tf32(v.x);
            Ast[kq * 4 + 1][m] = f2tf32(v.y);
            Ast[kq * 4 + 2][m] = f2tf32(v.z);
            Ast[kq * 4 + 3][m] = f2tf32(v.w);
        }
        // fill B tile (BK x BN)
#pragma unroll
        for (int idx = tid; idx < BK * (BN / 4); idx += 256) {
            int kk = idx / (BN / 4);
            int cq = idx % (BN / 4);
            float4 v = *(const float4*)&B[(size_t)(k0 + kk) * BN + cq * 4];
            Bs[kk][cq * 4 + 0] = f2tf32(v.x);
            Bs[kk][cq * 4 + 1] = f2tf32(v.y);
            Bs[kk][cq * 4 + 2] = f2tf32(v.z);
            Bs[kk][cq * 4 + 3] = f2tf32(v.w);
        }
        __syncthreads();

#pragma unroll
        for (int ks = 0; ks < BK / 8; ks++) {
            unsigned int a[2][4];
#pragma unroll
            for (int mt = 0; mt < 2; mt++) {
                int mb = m0 + mt * 16 + gid;
                a[mt][0] = Ast[ks * 8 + tig][mb];
                a[mt][1] = Ast[ks * 8 + tig][mb + 8];
                a[mt][2] = Ast[ks * 8 + tig + 4][mb];
                a[mt][3] = Ast[ks * 8 + tig + 4][mb + 8];
            }
#pragma unroll
            for (int nt = 0; nt < NT; nt++) {
                unsigned int b0 = Bs[ks * 8 + tig][n0 + nt * 8 + gid];
                unsigned int b1 = Bs[ks * 8 + tig + 4][n0 + nt * 8 + gid];
#pragma unroll
                for (int mt = 0; mt < 2; mt++) {
                    asm("mma.sync.aligned.m16n8k8.row.col.f32.tf32.tf32.f32 "
                        "{%0,%1,%2,%3}, {%4,%5,%6,%7}, {%8,%9}, {%0,%1,%2,%3};"
                        : "+f"(acc[mt][nt][0]), "+f"(acc[mt][nt][1]),
                          "+f"(acc[mt][nt][2]), "+f"(acc[mt][nt][3])
                        : "r"(a[mt][0]), "r"(a[mt][1]), "r"(a[mt][2]), "r"(a[mt][3]),
                          "r"(b0), "r"(b1));
                }
            }
        }
        __syncthreads();
    }

    // ---- epilogue: store C ----
#pragma unroll
    for (int mt = 0; mt < 2; mt++) {
#pragma unroll
        for (int nt = 0; nt < NT; nt++) {
            int col = n0 + nt * 8 + 2 * tig;
            int r0 = row0 + m0 + mt * 16 + gid;
            if (r0 < M)
                *(float2*)&C[(size_t)r0 * BN + col] = make_float2(acc[mt][nt][0], acc[mt][nt][1]);
            if (r0 + 8 < M)
                *(float2*)&C[(size_t)(r0 + 8) * BN + col] = make_float2(acc[mt][nt][2], acc[mt][nt][3]);
        }
    }

    // ---- epilogue: fused attention logits ----
    if (LAYER == 0) {
        // Each warp_n owns exactly 2 heads (head = col>>5 = warp_n*2 + (nt>>2)).
        // ps/pd per (mt, half, head_local); reduce over the 4 tig lanes.
        float ps[2][2][2], pd[2][2][2];
#pragma unroll
        for (int mt = 0; mt < 2; mt++)
#pragma unroll
            for (int hf = 0; hf < 2; hf++)
#pragma unroll
                for (int hl = 0; hl < 2; hl++) { ps[mt][hf][hl] = 0.f; pd[mt][hf][hl] = 0.f; }
#pragma unroll
        for (int mt = 0; mt < 2; mt++)
#pragma unroll
            for (int nt = 0; nt < NT; nt++) {
                int col = n0 + nt * 8 + 2 * tig;
                int hl = nt >> 2;
                float s0 = a_s[col], s1 = a_s[col + 1];
                float d0 = a_d[col], d1 = a_d[col + 1];
                ps[mt][0][hl] += acc[mt][nt][0] * s0 + acc[mt][nt][1] * s1;
                ps[mt][1][hl] += acc[mt][nt][2] * s0 + acc[mt][nt][3] * s1;
                pd[mt][0][hl] += acc[mt][nt][0] * d0 + acc[mt][nt][1] * d1;
                pd[mt][1][hl] += acc[mt][nt][2] * d0 + acc[mt][nt][3] * d1;
            }
#pragma unroll
        for (int mt = 0; mt < 2; mt++)
#pragma unroll
            for (int hf = 0; hf < 2; hf++)
#pragma unroll
                for (int hl = 0; hl < 2; hl++) {
                    float p = ps[mt][hf][hl], q = pd[mt][hf][hl];
                    p += __shfl_xor_sync(0xffffffffu, p, 1);
                    p += __shfl_xor_sync(0xffffffffu, p, 2);
                    q += __shfl_xor_sync(0xffffffffu, q, 1);
                    q += __shfl_xor_sync(0xffffffffu, q, 2);
                    ps[mt][hf][hl] = p; pd[mt][hf][hl] = q;
                }
        if (tig == 0) {
#pragma unroll
            for (int mt = 0; mt < 2; mt++)
#pragma unroll
                for (int hf = 0; hf < 2; hf++) {
                    int row = row0 + m0 + mt * 16 + hf * 8 + gid;
                    if (row < M) {
#pragma unroll
                        for (int hl = 0; hl < 2; hl++) {
                            int head = warp_n * 2 + hl;
                            g_als1[row * HEADS + head] = ps[mt][hf][hl];
                            g_ald1[row * HEADS + head] = pd[mt][hf][hl];
                        }
                    }
                }
        }
    } else {
        // Single head over 64 cols, split across warp_n -> combine in smem.
        float ps[2][2], pd[2][2];
#pragma unroll
        for (int mt = 0; mt < 2; mt++)
#pragma unroll
            for (int hf = 0; hf < 2; hf++) { ps[mt][hf] = 0.f; pd[mt][hf] = 0.f; }
#pragma unroll
        for (int mt = 0; mt < 2; mt++)
#pragma unroll
            for (int nt = 0; nt < NT; nt++) {
                int col = n0 + nt * 8 + 2 * tig;
                float s0 = a_s[col], s1 = a_s[col + 1];
                float d0 = a_d[col], d1 = a_d[col + 1];
                ps[mt][0] += acc[mt][nt][0] * s0 + acc[mt][nt][1] * s1;
                ps[mt][1] += acc[mt][nt][2] * s0 + acc[mt][nt][3] * s1;
                pd[mt][0] += acc[mt][nt][0] * d0 + acc[mt][nt][1] * d1;
                pd[mt][1] += acc[mt][nt][2] * d0 + acc[mt][nt][3] * d1;
            }
#pragma unroll
        for (int mt = 0; mt < 2; mt++)
#pragma unroll
            for (int hf = 0; hf < 2; hf++) {
                float p = ps[mt][hf], q = pd[mt][hf];
                p += __shfl_xor_sync(0xffffffffu, p, 1);
                p += __shfl_xor_sync(0xffffffffu, p, 2);
                q += __shfl_xor_sync(0xffffffffu, q, 1);
                q += __shfl_xor_sync(0xffffffffu, q, 2);
                if (tig == 0) {
                    int rl = m0 + mt * 16 + hf * 8 + gid;
                    atomicAdd(&sP[rl], p);
                    atomicAdd(&sD[rl], q);
                }
            }
        __syncthreads();
        if (tid < BM) {
            int row = row0 + tid;
            if (row < M) {
                g_als2[row] = sP[tid];
                g_ald2[row] = sD[tid];
            }
        }
    }
}

// ---------------- aggregation (warp per destination node, single pass) ------
// out = (sum_j e_j * h_j) / (sum_j e_j); exp is shift-free (scores bounded).
// Layer 1: all 8 lanes of a head group compute identical e, so each lane's
// running s is already the full per-head sum -> no warp reduction needed.
__global__ void k_agg1(const float* __restrict__ bias) {
    int w = (blockIdx.x * blockDim.x + threadIdx.x) >> 5;
    int lane = threadIdx.x & 31;
    if (w >= N_NODES) return;
    int beg = g_off[w], end = g_off[w + 1];
    int head = lane >> 3;
    float adh = g_ald1[w * HEADS + head];

    float4 acc = make_float4(0.f, 0.f, 0.f, 0.f);
    float s = 0.f;
    const float4* hp = (const float4*)g_h1;
#pragma unroll 2
    for (int j = beg; j < end; ++j) {
        int src = g_psrc[j];
        float als = g_als1[src * HEADS + head];
        float e = __expf(lrelu(als + adh));
        float4 hv = hp[(size_t)src * (H1DIM / 4) + lane];
        acc.x += hv.x * e; acc.y += hv.y * e; acc.z += hv.z * e; acc.w += hv.w * e;
        s += e;
    }
    float inv = 1.0f / (s + 1e-16f);

    float4 bv = ((const float4*)bias)[lane];
    float4 v;
    v.x = acc.x * inv + bv.x; v.y = acc.y * inv + bv.y;
    v.z = acc.z * inv + bv.z; v.w = acc.w * inv + bv.w;
    v.x = v.x > 0.f ? v.x : expm1f(v.x);
    v.y = v.y > 0.f ? v.y : expm1f(v.y);
    v.z = v.z > 0.f ? v.z : expm1f(v.z);
    v.w = v.w > 0.f ? v.w : expm1f(v.w);
    ((float4*)g_out1)[(size_t)w * (H1DIM / 4) + lane] = v;
}

// Layer 2: 64 ch = 256B row -> 16 lanes x float4 -> 2 edges per warp-iter.
__global__ void k_agg2(const float* __restrict__ bias, float* __restrict__ out) {
    int w = (blockIdx.x * blockDim.x + threadIdx.x) >> 5;
    int lane = threadIdx.x & 31;
    if (w >= N_NODES) return;
    int beg = g_off[w], end = g_off[w + 1];
    int half = lane >> 4;   // which edge of the pair
    int sl = lane & 15;     // channel group within row
    float ad = g_ald2[w];

    float4 acc = make_float4(0.f, 0.f, 0.f, 0.f);
    float s = 0.f;
    const float4* hp = (const float4*)g_h2;
    for (int j = beg + half; j < end; j += 2) {
        int src = g_psrc[j];
        float e = __expf(lrelu(g_als2[src] + ad));
        float4 hv = hp[(size_t)src * (OUT_C / 4) + sl];
        acc.x += hv.x * e; acc.y += hv.y * e; acc.z += hv.z * e; acc.w += hv.w * e;
        s += e;
    }
    // combine the two edge-halves
    s += __shfl_xor_sync(0xffffffffu, s, 16);
    acc.x += __shfl_xor_sync(0xffffffffu, acc.x, 16);
    acc.y += __shfl_xor_sync(0xffffffffu, acc.y, 16);
    acc.z += __shfl_xor_sync(0xffffffffu, acc.z, 16);
    acc.w += __shfl_xor_sync(0xffffffffu, acc.w, 16);
    if (half == 0) {
        float inv = 1.0f / (s + 1e-16f);
        float4 bv = ((const float4*)bias)[sl];
        float4 v;
        v.x = acc.x * inv + bv.x; v.y = acc.y * inv + bv.y;
        v.z = acc.z * inv + bv.z; v.w = acc.w * inv + bv.w;
        ((float4*)out)[(size_t)w * (OUT_C / 4) + sl] = v;
    }
}

// ---------------- launch -----------------------------------------------------
extern "C" void kernel_launch(void* const* d_in, const int* in_sizes, int n_in,
                              void* d_out, int out_size) {
    const float*      x      = (const float*)d_in[0];
    const void*       eidx   = d_in[1];               // int32 or int64, detected on device
    const float*      W1     = (const float*)d_in[2];
    const float*      a_src1 = (const float*)d_in[3];
    const float*      a_dst1 = (const float*)d_in[4];
    const float*      b1     = (const float*)d_in[5];
    const float*      W2     = (const float*)d_in[6];
    const float*      a_src2 = (const float*)d_in[7];
    const float*      a_dst2 = (const float*)d_in[8];
    const float*      b2     = (const float*)d_in[9];
    float*            out    = (float*)d_out;

    const int node_blocks = NODE_BLOCKS;
    const int edge_blocks = (NUM_E + 255) / 256;
    const int warp_blocks = (N_NODES * 32 + 255) / 256;
    const int gemm_blocks = (N_NODES + 127) / 128;

    // CSR build
    k_zero_detect<<<node_blocks + 1, 256>>>(eidx);
    k_convert_hist<<<edge_blocks, 256>>>(eidx);
    k_scan1<<<SCAN_NBLK, SCAN_B>>>();
    k_scan2<<<1, SCAN_B>>>();
    k_scan3<<<node_blocks, 256>>>();
    k_scatter<<<edge_blocks, 256>>>();

    // Layer 1 (GEMM + fused logits)
    k_gemm_tc<0, 128><<<gemm_blocks, 256>>>(x, W1, a_src1, a_dst1);
    k_agg1<<<warp_blocks, 256>>>(b1);

    // Layer 2 (GEMM + fused logits)
    k_gemm_tc<1, 64><<<gemm_blocks, 256>>>(nullptr, W2, a_src2, a_dst2);
    k_agg2<<<warp_blocks, 256>>>(b2, out);
}

// round 14
// speedup vs baseline: 1.7339x; 1.0027x over previous
#include <cuda_runtime.h>
#include <cuda_fp16.h>

// Problem constants (fixed shapes for this problem instance)
#define N_NODES 100000
#define NUM_E   1600000
#define IN_C    128
#define HID     32
#define HEADS   4
#define H1DIM   128   // HEADS*HID
#define OUT_C   64
#define NEG_SLOPE 0.2f

#define SCAN_B 512
#define SCAN_NBLK ((N_NODES + SCAN_B - 1) / SCAN_B)   // 196
#define NODE_BLOCKS ((N_NODES + 255) / 256)

// ---------------- scratch (device globals; no runtime allocation) -----------
__device__ int   g_is64;                 // edge_index dtype flag (1 = int64)
__device__ int   g_src[NUM_E];
__device__ int   g_dst[NUM_E];
__device__ int   g_psrc[NUM_E];          // CSR-by-dst permuted src ids
__device__ int   g_deg[N_NODES];
__device__ int   g_off[N_NODES + 1];
__device__ int   g_cur[N_NODES];
__device__ int   g_bsum[SCAN_B];
__device__ __align__(16) __half g_h1[(size_t)N_NODES * H1DIM];   // fp16 features
__device__ __align__(16) float  g_out1[(size_t)N_NODES * H1DIM];
__device__ __align__(16) float  g_als1[N_NODES * HEADS];
__device__ __align__(16) float  g_ald1[N_NODES * HEADS];
__device__ __align__(16) __half g_h2[(size_t)N_NODES * OUT_C];   // fp16 features
__device__ __align__(16) float  g_als2[N_NODES];
__device__ __align__(16) float  g_ald2[N_NODES];

__device__ __forceinline__ float lrelu(float x) {
    return x >= 0.0f ? x : NEG_SLOPE * x;
}

__device__ __forceinline__ unsigned int f2tf32(float x) {
    unsigned int r;
    asm("cvt.rna.tf32.f32 %0, %1;" : "=r"(r) : "f"(x));
    return r;
}

// ---------------- CSR build --------------------------------------------------
// zero_deg fused with dtype detection (last block does detect).
__global__ void k_zero_detect(const void* __restrict__ ei) {
    if (blockIdx.x == NODE_BLOCKS) {
        __shared__ int ok;
        if (threadIdx.x == 0) ok = 1;
        __syncthreads();
        const long long* p = (const long long*)ei;
        for (int i = threadIdx.x; i < 2048; i += blockDim.x) {
            long long v = p[i];
            if (v < 0 || v >= N_NODES) ok = 0;
        }
        __syncthreads();
        if (threadIdx.x == 0) g_is64 = ok;
        return;
    }
    int i = blockIdx.x * blockDim.x + threadIdx.x;
    if (i < N_NODES) g_deg[i] = 0;
}

__global__ void k_convert_hist(const void* __restrict__ ei) {
    int i = blockIdx.x * blockDim.x + threadIdx.x;
    if (i < NUM_E) {
        int s, d;
        if (g_is64) {
            const long long* p = (const long long*)ei;
            s = (int)p[i];
            d = (int)p[NUM_E + i];
        } else {
            const int* p = (const int*)ei;
            s = p[i];
            d = p[NUM_E + i];
        }
        s = min(max(s, 0), N_NODES - 1);
        d = min(max(d, 0), N_NODES - 1);
        g_src[i] = s;
        g_dst[i] = d;
        atomicAdd(&g_deg[d], 1);
    }
}

__global__ void k_scan1() {
    __shared__ int sh[SCAN_B];
    int tid = threadIdx.x;
    int i = blockIdx.x * SCAN_B + tid;
    int v = (i < N_NODES) ? g_deg[i] : 0;
    sh[tid] = v;
    __syncthreads();
    for (int o = 1; o < SCAN_B; o <<= 1) {
        int t = (tid >= o) ? sh[tid - o] : 0;
        __syncthreads();
        sh[tid] += t;
        __syncthreads();
    }
    if (i < N_NODES) g_off[i] = sh[tid] - v;
    if (tid == SCAN_B - 1) g_bsum[blockIdx.x] = sh[tid];
}

// scan of the 196 block sums folded into the per-node fixup (every block
// redoes the tiny 196-element scan in smem; removes the serial scan2 launch).
__global__ void k_scan23() {
    __shared__ int sh[256];
    __shared__ int sexc[256];
    int tid = threadIdx.x;
    int v = (tid < SCAN_NBLK) ? g_bsum[tid] : 0;
    sh[tid] = v;
    __syncthreads();
    for (int o = 1; o < 256; o <<= 1) {
        int t = (tid >= o) ? sh[tid - o] : 0;
        __syncthreads();
        sh[tid] += t;
        __syncthreads();
    }
    sexc[tid] = sh[tid] - v;
    __syncthreads();
    int i = blockIdx.x * blockDim.x + tid;
    if (i < N_NODES) {
        int o = g_off[i] + sexc[i / SCAN_B];
        g_off[i] = o;
        g_cur[i] = o;
    }
    if (i == 0) g_off[N_NODES] = NUM_E;
}

__global__ void k_scatter() {
    int i = blockIdx.x * blockDim.x + threadIdx.x;
    if (i < NUM_E) {
        int d = g_dst[i];
        int pos = atomicAdd(&g_cur[d], 1);
        g_psrc[pos] = g_src[i];
    }
}

// ---------------- tf32 tensor-core GEMM with fused attention logits ----------
// LAYER 0: g_h1 [N,128](fp16) = A_param(x) [N,128] * W1; logits -> g_als1/g_ald1
// LAYER 1: g_h2 [N, 64](fp16) = g_out1     [N,128] * W2; logits -> g_als2/g_ald2
// mma.sync.aligned.m16n8k8 tf32. 256 threads, BM=128, warps 4(m) x 2(n).
// Logits computed from fp32 accumulators (full precision); C stored fp16.
template <int LAYER, int BN>
__global__ void __launch_bounds__(256) k_gemm_tc(const float* __restrict__ A_param,
                                                 const float* __restrict__ B,
                                                 const float* __restrict__ a_s,
                                                 const float* __restrict__ a_d) {
    constexpr int BM = 128;
    constexpr int BK = 32;
    constexpr int K = 128;
    constexpr int M = N_NODES;
    constexpr int NT = BN / 2 / 8;   // n-tiles per warp (8 or 4)
    constexpr int APAD = 4;

    const float* __restrict__ A = (LAYER == 0) ? A_param : (const float*)g_out1;
    __half* __restrict__ C = (LAYER == 0) ? (__half*)g_h1 : (__half*)g_h2;

    __shared__ unsigned int Ast[BK][BM + APAD];   // transposed: Ast[k][m]
    __shared__ unsigned int Bs[BK][BN + APAD];    // Bs[k][n]
    __shared__ float sP[BM], sD[BM];              // layer-2 logit combine

    int tid = threadIdx.x;
    int wid = tid >> 5;
    int lane = tid & 31;
    int gid = lane >> 2;     // 0..7
    int tig = lane & 3;      // 0..3
    int warp_m = wid >> 1;   // 0..3
    int warp_n = wid & 1;    // 0..1
    int m0 = warp_m * 32;
    int n0 = warp_n * (BN / 2);
    int row0 = blockIdx.x * BM;

    if (LAYER == 1 && tid < BM) { sP[tid] = 0.f; sD[tid] = 0.f; }

    float acc[2][NT][4];
#pragma unroll
    for (int mt = 0; mt < 2; mt++)
#pragma unroll
        for (int nt = 0; nt < NT; nt++)
#pragma unroll
            for (int c = 0; c < 4; c++) acc[mt][nt][c] = 0.f;

    for (int k0 = 0; k0 < K; k0 += BK) {
        // fill A tile (BM x BK) transposed, with tf32 convert
#pragma unroll
        for (int idx = tid; idx < BM * (BK / 4); idx += 256) {
            int m = idx >> 3;            // BK/4 == 8
            int kq = idx & 7;
            int gr = row0 + m;
            float4 v = make_float4(0.f, 0.f, 0.f, 0.f);
            if (gr < M) v = *(const float4*)&A[(size_t)gr * K + k0 + kq * 4];
            Ast[kq * 4 + 0][m] = f2tf32(v.x);
            Ast[kq * 4 + 1][m] = f2tf32(v.y);
            Ast[kq * 4 + 2][m] = f2tf32(v.z);
            Ast[kq * 4 + 3][m] = f2tf32(v.w);
        }
        // fill B tile (BK x BN)
#pragma unroll
        for (int idx = tid; idx < BK * (BN / 4); idx += 256) {
            int kk = idx / (BN / 4);
            int cq = idx % (BN / 4);
            float4 v = *(const float4*)&B[(size_t)(k0 + kk) * BN + cq * 4];
            Bs[kk][cq * 4 + 0] = f2tf32(v.x);
            Bs[kk][cq * 4 + 1] = f2tf32(v.y);
            Bs[kk][cq * 4 + 2] = f2tf32(v.z);
            Bs[kk][cq * 4 + 3] = f2tf32(v.w);
        }
        __syncthreads();

#pragma unroll
        for (int ks = 0; ks < BK / 8; ks++) {
            unsigned int a[2][4];
#pragma unroll
            for (int mt = 0; mt < 2; mt++) {
                int mb = m0 + mt * 16 + gid;
                a[mt][0] = Ast[ks * 8 + tig][mb];
                a[mt][1] = Ast[ks * 8 + tig][mb + 8];
                a[mt][2] = Ast[ks * 8 + tig + 4][mb];
                a[mt][3] = Ast[ks * 8 + tig + 4][mb + 8];
            }
#pragma unroll
            for (int nt = 0; nt < NT; nt++) {
                unsigned int b0 = Bs[ks * 8 + tig][n0 + nt * 8 + gid];
                unsigned int b1 = Bs[ks * 8 + tig + 4][n0 + nt * 8 + gid];
#pragma unroll
                for (int mt = 0; mt < 2; mt++) {
                    asm("mma.sync.aligned.m16n8k8.row.col.f32.tf32.tf32.f32 "
                        "{%0,%1,%2,%3}, {%4,%5,%6,%7}, {%8,%9}, {%0,%1,%2,%3};"
                        : "+f"(acc[mt][nt][0]), "+f"(acc[mt][nt][1]),
                          "+f"(acc[mt][nt][2]), "+f"(acc[mt][nt][3])
                        : "r"(a[mt][0]), "r"(a[mt][1]), "r"(a[mt][2]), "r"(a[mt][3]),
                          "r"(b0), "r"(b1));
                }
            }
        }
        __syncthreads();
    }

    // ---- epilogue: store C as fp16 ----
#pragma unroll
    for (int mt = 0; mt < 2; mt++) {
#pragma unroll
        for (int nt = 0; nt < NT; nt++) {
            int col = n0 + nt * 8 + 2 * tig;
            int r0 = row0 + m0 + mt * 16 + gid;
            if (r0 < M)
                *(__half2*)&C[(size_t)r0 * BN + col] =
                    __floats2half2_rn(acc[mt][nt][0], acc[mt][nt][1]);
            if (r0 + 8 < M)
                *(__half2*)&C[(size_t)(r0 + 8) * BN + col] =
                    __floats2half2_rn(acc[mt][nt][2], acc[mt][nt][3]);
        }
    }

    // ---- epilogue: fused attention logits (fp32 accumulators) ----
    if (LAYER == 0) {
        float ps[2][2][2], pd[2][2][2];
#pragma unroll
        for (int mt = 0; mt < 2; mt++)
#pragma unroll
            for (int hf = 0; hf < 2; hf++)
#pragma unroll
                for (int hl = 0; hl < 2; hl++) { ps[mt][hf][hl] = 0.f; pd[mt][hf][hl] = 0.f; }
#pragma unroll
        for (int mt = 0; mt < 2; mt++)
#pragma unroll
            for (int nt = 0; nt < NT; nt++) {
                int col = n0 + nt * 8 + 2 * tig;
                int hl = nt >> 2;
                float s0 = a_s[col], s1 = a_s[col + 1];
                float d0 = a_d[col], d1 = a_d[col + 1];
                ps[mt][0][hl] += acc[mt][nt][0] * s0 + acc[mt][nt][1] * s1;
                ps[mt][1][hl] += acc[mt][nt][2] * s0 + acc[mt][nt][3] * s1;
                pd[mt][0][hl] += acc[mt][nt][0] * d0 + acc[mt][nt][1] * d1;
                pd[mt][1][hl] += acc[mt][nt][2] * d0 + acc[mt][nt][3] * d1;
            }
#pragma unroll
        for (int mt = 0; mt < 2; mt++)
#pragma unroll
            for (int hf = 0; hf < 2; hf++)
#pragma unroll
                for (int hl = 0; hl < 2; hl++) {
                    float p = ps[mt][hf][hl], q = pd[mt][hf][hl];
                    p += __shfl_xor_sync(0xffffffffu, p, 1);
                    p += __shfl_xor_sync(0xffffffffu, p, 2);
                    q += __shfl_xor_sync(0xffffffffu, q, 1);
                    q += __shfl_xor_sync(0xffffffffu, q, 2);
                    ps[mt][hf][hl] = p; pd[mt][hf][hl] = q;
                }
        if (tig == 0) {
#pragma unroll
            for (int mt = 0; mt < 2; mt++)
#pragma unroll
                for (int hf = 0; hf < 2; hf++) {
                    int row = row0 + m0 + mt * 16 + hf * 8 + gid;
                    if (row < M) {
#pragma unroll
                        for (int hl = 0; hl < 2; hl++) {
                            int head = warp_n * 2 + hl;
                            g_als1[row * HEADS + head] = ps[mt][hf][hl];
                            g_ald1[row * HEADS + head] = pd[mt][hf][hl];
                        }
                    }
                }
        }
    } else {
        float ps[2][2], pd[2][2];
#pragma unroll
        for (int mt = 0; mt < 2; mt++)
#pragma unroll
            for (int hf = 0; hf < 2; hf++) { ps[mt][hf] = 0.f; pd[mt][hf] = 0.f; }
#pragma unroll
        for (int mt = 0; mt < 2; mt++)
#pragma unroll
            for (int nt = 0; nt < NT; nt++) {
                int col = n0 + nt * 8 + 2 * tig;
                float s0 = a_s[col], s1 = a_s[col + 1];
                float d0 = a_d[col], d1 = a_d[col + 1];
                ps[mt][0] += acc[mt][nt][0] * s0 + acc[mt][nt][1] * s1;
                ps[mt][1] += acc[mt][nt][2] * s0 + acc[mt][nt][3] * s1;
                pd[mt][0] += acc[mt][nt][0] * d0 + acc[mt][nt][1] * d1;
                pd[mt][1] += acc[mt][nt][2] * d0 + acc[mt][nt][3] * d1;
            }
#pragma unroll
        for (int mt = 0; mt < 2; mt++)
#pragma unroll
            for (int hf = 0; hf < 2; hf++) {
                float p = ps[mt][hf], q = pd[mt][hf];
                p += __shfl_xor_sync(0xffffffffu, p, 1);
                p += __shfl_xor_sync(0xffffffffu, p, 2);
                q += __shfl_xor_sync(0xffffffffu, q, 1);
                q += __shfl_xor_sync(0xffffffffu, q, 2);
                if (tig == 0) {
                    int rl = m0 + mt * 16 + hf * 8 + gid;
                    atomicAdd(&sP[rl], p);
                    atomicAdd(&sD[rl], q);
                }
            }
        __syncthreads();
        if (tid < BM) {
            int row = row0 + tid;
            if (row < M) {
                g_als2[row] = sP[tid];
                g_ald2[row] = sD[tid];
            }
        }
    }
}

// ---------------- aggregation (warp per destination node, single pass) ------
// out = (sum_j e_j * h_j) / (sum_j e_j); h gathered in fp16, accumulated fp32.
__global__ void k_agg1(const float* __restrict__ bias) {
    int w = (blockIdx.x * blockDim.x + threadIdx.x) >> 5;
    int lane = threadIdx.x & 31;
    if (w >= N_NODES) return;
    int beg = g_off[w], end = g_off[w + 1];
    int head = lane >> 3;
    float adh = g_ald1[w * HEADS + head];

    float4 acc = make_float4(0.f, 0.f, 0.f, 0.f);
    float s = 0.f;
    const uint2* hp = (const uint2*)g_h1;   // 4 halves per uint2; row = 32 uint2
#pragma unroll 2
    for (int j = beg; j < end; ++j) {
        int src = g_psrc[j];
        float als = g_als1[src * HEADS + head];
        float e = __expf(lrelu(als + adh));
        uint2 hv = hp[(size_t)src * (H1DIM / 4) + lane];
        float2 f0 = __half22float2(*(__half2*)&hv.x);
        float2 f1 = __half22float2(*(__half2*)&hv.y);
        acc.x += f0.x * e; acc.y += f0.y * e; acc.z += f1.x * e; acc.w += f1.y * e;
        s += e;
    }
    float inv = 1.0f / (s + 1e-16f);

    float4 bv = ((const float4*)bias)[lane];
    float4 v;
    v.x = acc.x * inv + bv.x; v.y = acc.y * inv + bv.y;
    v.z = acc.z * inv + bv.z; v.w = acc.w * inv + bv.w;
    v.x = v.x > 0.f ? v.x : expm1f(v.x);
    v.y = v.y > 0.f ? v.y : expm1f(v.y);
    v.z = v.z > 0.f ? v.z : expm1f(v.z);
    v.w = v.w > 0.f ? v.w : expm1f(v.w);
    ((float4*)g_out1)[(size_t)w * (H1DIM / 4) + lane] = v;
}

// Layer 2: 64 ch -> 16 lanes x 4 halves -> 2 edges per warp-iter.
__global__ void k_agg2(const float* __restrict__ bias, float* __restrict__ out) {
    int w = (blockIdx.x * blockDim.x + threadIdx.x) >> 5;
    int lane = threadIdx.x & 31;
    if (w >= N_NODES) return;
    int beg = g_off[w], end = g_off[w + 1];
    int half = lane >> 4;   // which edge of the pair
    int sl = lane & 15;     // channel group within row
    float ad = g_ald2[w];

    float4 acc = make_float4(0.f, 0.f, 0.f, 0.f);
    float s = 0.f;
    const uint2* hp = (const uint2*)g_h2;   // row = 16 uint2
    for (int j = beg + half; j < end; j += 2) {
        int src = g_psrc[j];
        float e = __expf(lrelu(g_als2[src] + ad));
        uint2 hv = hp[(size_t)src * (OUT_C / 4) + sl];
        float2 f0 = __half22float2(*(__half2*)&hv.x);
        float2 f1 = __half22float2(*(__half2*)&hv.y);
        acc.x += f0.x * e; acc.y += f0.y * e; acc.z += f1.x * e; acc.w += f1.y * e;
        s += e;
    }
    // combine the two edge-halves
    s += __shfl_xor_sync(0xffffffffu, s, 16);
    acc.x += __shfl_xor_sync(0xffffffffu, acc.x, 16);
    acc.y += __shfl_xor_sync(0xffffffffu, acc.y, 16);
    acc.z += __shfl_xor_sync(0xffffffffu, acc.z, 16);
    acc.w += __shfl_xor_sync(0xffffffffu, acc.w, 16);
    if (half == 0) {
        float inv = 1.0f / (s + 1e-16f);
        float4 bv = ((const float4*)bias)[sl];
        float4 v;
        v.x = acc.x * inv + bv.x; v.y = acc.y * inv + bv.y;
        v.z = acc.z * inv + bv.z; v.w = acc.w * inv + bv.w;
        ((float4*)out)[(size_t)w * (OUT_C / 4) + sl] = v;
    }
}

// ---------------- launch -----------------------------------------------------
extern "C" void kernel_launch(void* const* d_in, const int* in_sizes, int n_in,
                              void* d_out, int out_size) {
    const float*      x      = (const float*)d_in[0];
    const void*       eidx   = d_in[1];               // int32 or int64, detected on device
    const float*      W1     = (const float*)d_in[2];
    const float*      a_src1 = (const float*)d_in[3];
    const float*      a_dst1 = (const float*)d_in[4];
    const float*      b1     = (const float*)d_in[5];
    const float*      W2     = (const float*)d_in[6];
    const float*      a_src2 = (const float*)d_in[7];
    const float*      a_dst2 = (const float*)d_in[8];
    const float*      b2     = (const float*)d_in[9];
    float*            out    = (float*)d_out;

    const int node_blocks = NODE_BLOCKS;
    const int edge_blocks = (NUM_E + 255) / 256;
    const int warp_blocks = (N_NODES * 32 + 255) / 256;
    const int gemm_blocks = (N_NODES + 127) / 128;

    // CSR build
    k_zero_detect<<<node_blocks + 1, 256>>>(eidx);
    k_convert_hist<<<edge_blocks, 256>>>(eidx);
    k_scan1<<<SCAN_NBLK, SCAN_B>>>();
    k_scan23<<<node_blocks, 256>>>();
    k_scatter<<<edge_blocks, 256>>>();

    // Layer 1 (GEMM + fused logits)
    k_gemm_tc<0, 128><<<gemm_blocks, 256>>>(x, W1, a_src1, a_dst1);
    k_agg1<<<warp_blocks, 256>>>(b1);

    // Layer 2 (GEMM + fused logits)
    k_gemm_tc<1, 64><<<gemm_blocks, 256>>>(nullptr, W2, a_src2, a_dst2);
    k_agg2<<<warp_blocks, 256>>>(b2, out);
}